// round 1
// baseline (speedup 1.0000x reference)
#include <cuda_runtime.h>
#include <cstdint>

#define L_SEQ 4096
#define D_DIM 1024
#define BATCH 4
#define M_TOT (BATCH * L_SEQ)   // 16384

// 64 MB scratch for u_proj = silu(u @ Wp^T + bp)
__device__ float g_uproj[(size_t)M_TOT * D_DIM];

__device__ __forceinline__ float silu_f(float x) {
    return x / (1.0f + __expf(-x));
}

__device__ __forceinline__ uint32_t f2tf32(float x) {
    uint32_t r;
    asm("cvt.rna.tf32.f32 %0, %1;" : "=r"(r) : "f"(x));
    return r;
}

// ---------------------------------------------------------------------------
// Kernel 1: u_proj[m, n] = silu( sum_k U[m,k] * Wp[n,k] + bp[n] )
// A row-major (M x K), B = Wp row-major (N x K)  -> mma row.col directly.
// Block tile 128x128x16, 8 warps (2x4), warp tile 64x32, m16n8k8 tf32 MMA.
// ---------------------------------------------------------------------------
#define BM 128
#define BN 128
#define BKT 16
#define SSTR 20   // smem row stride in floats (16 + 4 pad, conflict-free frags)

__global__ __launch_bounds__(256, 1)
void gemm_silu_kernel(const float* __restrict__ U,
                      const float* __restrict__ Wp,
                      const float* __restrict__ bp)
{
    __shared__ float As[BM][SSTR];
    __shared__ float Bs[BN][SSTR];

    const int tid  = threadIdx.x;
    const int lane = tid & 31;
    const int warp = tid >> 5;
    const int wm = warp >> 2;       // 0..1
    const int wn = warp & 3;        // 0..3
    const int gid = lane >> 2;      // 0..7
    const int tig = lane & 3;       // 0..3

    const int m0 = blockIdx.y * BM;
    const int n0 = blockIdx.x * BN;

    float c[4][4][4];
    #pragma unroll
    for (int i = 0; i < 4; i++)
        #pragma unroll
        for (int j = 0; j < 4; j++)
            #pragma unroll
            for (int r = 0; r < 4; r++)
                c[i][j][r] = 0.0f;

    for (int kt = 0; kt < D_DIM; kt += BKT) {
        // Stage A tile (convert to tf32 bit pattern on the way in)
        #pragma unroll
        for (int i = tid; i < BM * BKT / 4; i += 256) {
            int row = i >> 2;
            int k4  = (i & 3) << 2;
            float4 v = *(const float4*)(U + (size_t)(m0 + row) * D_DIM + kt + k4);
            uint4 t;
            t.x = f2tf32(v.x); t.y = f2tf32(v.y);
            t.z = f2tf32(v.z); t.w = f2tf32(v.w);
            *(uint4*)&As[row][k4] = t;
        }
        // Stage B tile
        #pragma unroll
        for (int i = tid; i < BN * BKT / 4; i += 256) {
            int row = i >> 2;
            int k4  = (i & 3) << 2;
            float4 v = *(const float4*)(Wp + (size_t)(n0 + row) * D_DIM + kt + k4);
            uint4 t;
            t.x = f2tf32(v.x); t.y = f2tf32(v.y);
            t.z = f2tf32(v.z); t.w = f2tf32(v.w);
            *(uint4*)&Bs[row][k4] = t;
        }
        __syncthreads();

        #pragma unroll
        for (int kk = 0; kk < BKT; kk += 8) {
            uint32_t a[4][4], b[4][2];
            #pragma unroll
            for (int mt = 0; mt < 4; mt++) {
                int r0 = wm * 64 + mt * 16 + gid;
                const uint32_t* p0 = (const uint32_t*)&As[r0][kk + tig];
                const uint32_t* p1 = (const uint32_t*)&As[r0 + 8][kk + tig];
                a[mt][0] = p0[0];
                a[mt][1] = p1[0];
                a[mt][2] = p0[4];
                a[mt][3] = p1[4];
            }
            #pragma unroll
            for (int nt = 0; nt < 4; nt++) {
                int rr = wn * 32 + nt * 8 + gid;
                const uint32_t* p = (const uint32_t*)&Bs[rr][kk + tig];
                b[nt][0] = p[0];
                b[nt][1] = p[4];
            }
            #pragma unroll
            for (int mt = 0; mt < 4; mt++)
                #pragma unroll
                for (int nt = 0; nt < 4; nt++) {
                    asm volatile(
                        "mma.sync.aligned.m16n8k8.row.col.f32.tf32.tf32.f32 "
                        "{%0,%1,%2,%3}, {%4,%5,%6,%7}, {%8,%9}, {%0,%1,%2,%3};"
                        : "+f"(c[mt][nt][0]), "+f"(c[mt][nt][1]),
                          "+f"(c[mt][nt][2]), "+f"(c[mt][nt][3])
                        : "r"(a[mt][0]), "r"(a[mt][1]), "r"(a[mt][2]), "r"(a[mt][3]),
                          "r"(b[nt][0]), "r"(b[nt][1]));
                }
        }
        __syncthreads();
    }

    // Epilogue: + bp, silu, store float2 pairs
    #pragma unroll
    for (int mt = 0; mt < 4; mt++) {
        int row0 = m0 + wm * 64 + mt * 16 + gid;
        #pragma unroll
        for (int nt = 0; nt < 4; nt++) {
            int col = n0 + wn * 32 + nt * 8 + tig * 2;
            float bp0 = __ldg(bp + col);
            float bp1 = __ldg(bp + col + 1);
            float2 v0 = make_float2(silu_f(c[mt][nt][0] + bp0),
                                    silu_f(c[mt][nt][1] + bp1));
            *(float2*)(g_uproj + (size_t)row0 * D_DIM + col) = v0;
            float2 v1 = make_float2(silu_f(c[mt][nt][2] + bp0),
                                    silu_f(c[mt][nt][3] + bp1));
            *(float2*)(g_uproj + (size_t)(row0 + 8) * D_DIM + col) = v1;
        }
    }
}

// ---------------------------------------------------------------------------
// Kernel 2: h = silu(dwconv_k3(u, w1, b1)); y = dwconv_k128(h, w2, b2) * uproj
// Block: 32 channels x 128 l-positions. blockDim (32, 8): x = channel, y = l
// worker. h staged in smem [256][32] (channel-major -> conflict-free).
// Inner loop: rolling 8-register window, per tap: 2 LDS + 8 FMA (FMA-bound).
// ---------------------------------------------------------------------------
#define LT 128
#define CH 32
#define HROWS (LT + 128)   // 256

__global__ __launch_bounds__(256, 1)
void conv_fused_kernel(const float* __restrict__ u,
                       const float* __restrict__ w1,
                       const float* __restrict__ b1,
                       const float* __restrict__ w2,
                       const float* __restrict__ b2,
                       float* __restrict__ out)
{
    __shared__ float h_s[HROWS][CH];     // 32 KB
    __shared__ float w2_s[128][CH];      // 16 KB

    const int c   = threadIdx.x;               // 0..31
    const int yy  = threadIdx.y;               // 0..7
    const int tid = c + yy * 32;

    const int chunk = blockIdx.x;              // 0..31 channel chunk
    const int lt    = blockIdx.y;              // 0..31 l tile
    const int bb    = blockIdx.z;              // 0..3 batch
    const int tile_start = lt * LT;
    const int cglob = chunk * CH + c;

    // Stage w2 tile
    #pragma unroll
    for (int i = tid; i < 128 * CH; i += 256) {
        int j  = i >> 5;
        int cc = i & 31;
        w2_s[j][cc] = w2[(size_t)j * D_DIM + chunk * CH + cc];
    }

    // Per-thread conv1 weights (channel fixed = cglob for all phase-1 work,
    // since the phase-1 loop stride 256 keeps (i & 31) == (tid & 31) == c)
    const float w1_0 = __ldg(w1 + 0 * D_DIM + cglob);
    const float w1_1 = __ldg(w1 + 1 * D_DIM + cglob);
    const float w1_2 = __ldg(w1 + 2 * D_DIM + cglob);
    const float b1c  = __ldg(b1 + cglob);

    // Phase 1: h for local rows [0, HROWS) -> global l = tile_start-127+row
    const float* ub = u + (size_t)bb * L_SEQ * D_DIM + cglob;
    for (int i = tid; i < HROWS * CH; i += 256) {
        int hl = i >> 5;
        int l  = tile_start - 127 + hl;
        float hv = 0.0f;
        if (l >= 0 && l < L_SEQ) {
            float x2 = ub[(size_t)l * D_DIM];
            float x1 = (l >= 1) ? ub[(size_t)(l - 1) * D_DIM] : 0.0f;
            float x0 = (l >= 2) ? ub[(size_t)(l - 2) * D_DIM] : 0.0f;
            float v = fmaf(x0, w1_0, fmaf(x1, w1_1, fmaf(x2, w1_2, b1c)));
            hv = silu_f(v);
        }
        h_s[hl][c] = hv;
    }
    __syncthreads();

    // Phase 2: conv2 (k=128) + bias, multiply by u_proj, store
    const float b2c = __ldg(b2 + cglob);
    const float* up = g_uproj + ((size_t)bb * L_SEQ + tile_start) * D_DIM + cglob;
    float* op = out + ((size_t)bb * L_SEQ + tile_start) * D_DIM + cglob;

    #pragma unroll
    for (int g = 0; g < 2; g++) {
        const int base = yy * 16 + g * 8;   // local l of first output in group
        float acc[8];
        float hreg[8];
        #pragma unroll
        for (int r = 0; r < 8; r++) {
            acc[r]  = 0.0f;
            hreg[r] = h_s[base + r][c];
        }
        // y[l] = sum_{j=0..127} h[l-127+j]*w2[j]; local h row = (l-tile_start)+j
        #pragma unroll 8
        for (int j = 0; j < 128; j++) {
            float w = w2_s[j][c];
            #pragma unroll
            for (int r = 0; r < 8; r++)
                acc[r] = fmaf(hreg[(j + r) & 7], w, acc[r]);
            // slide window: load h[base + j + 8] (row <= 255, in bounds;
            // the j==127 load is dead but harmless)
            hreg[j & 7] = h_s[(base + j + 8) < HROWS ? (base + j + 8) : (HROWS - 1)][c];
        }
        #pragma unroll
        for (int r = 0; r < 8; r++) {
            int lo = base + r;
            float y = (acc[r] + b2c) * up[(size_t)lo * D_DIM];
            op[(size_t)lo * D_DIM] = y;
        }
    }
}

// ---------------------------------------------------------------------------
extern "C" void kernel_launch(void* const* d_in, const int* in_sizes, int n_in,
                              void* d_out, int out_size)
{
    const float* u  = (const float*)d_in[0];
    const float* w1 = (const float*)d_in[1];
    const float* b1 = (const float*)d_in[2];
    const float* w2 = (const float*)d_in[3];
    const float* b2 = (const float*)d_in[4];
    const float* Wp = (const float*)d_in[5];
    const float* bp = (const float*)d_in[6];
    float* out = (float*)d_out;

    dim3 g1(D_DIM / BN, M_TOT / BM);   // (8, 128)
    gemm_silu_kernel<<<g1, 256>>>(u, Wp, bp);

    dim3 g2(D_DIM / CH, L_SEQ / LT, BATCH);  // (32, 32, 4)
    conv_fused_kernel<<<g2, dim3(32, 8)>>>(u, w1, b1, w2, b2, out);
}

// round 3
// speedup vs baseline: 2.1823x; 2.1823x over previous
#include <cuda_runtime.h>
#include <cuda_fp16.h>
#include <cstdint>

#define L_SEQ 4096
#define D_DIM 1024
#define BATCH 4
#define M_TOT 16384

// scratch
__device__ float  g_uproj[(size_t)M_TOT * D_DIM];   // 64 MB
__device__ __half g_Uh[(size_t)M_TOT * D_DIM];      // 32 MB
__device__ __half g_Wh[(size_t)D_DIM * D_DIM];      // 2 MB

__device__ __forceinline__ float silu_f(float x) {
    return x / (1.0f + __expf(-x));
}

__device__ __forceinline__ uint32_t smem_u32(const void* p) {
    uint32_t a;
    asm("{ .reg .u64 t; cvta.to.shared.u64 t, %1; cvt.u32.u64 %0, t; }"
        : "=r"(a) : "l"(p));
    return a;
}

// ---------------------------------------------------------------------------
// Kernel 0: convert U and Wp to fp16 (RNE)
// ---------------------------------------------------------------------------
__global__ void __launch_bounds__(256)
convert_kernel(const float* __restrict__ U, const float* __restrict__ Wp)
{
    const size_t nU = (size_t)M_TOT * D_DIM / 4;
    const size_t nW = (size_t)D_DIM * D_DIM / 4;
    const size_t stride = (size_t)gridDim.x * blockDim.x;
    for (size_t i = (size_t)blockIdx.x * blockDim.x + threadIdx.x;
         i < nU + nW; i += stride) {
        float4 v = (i < nU) ? ((const float4*)U)[i] : ((const float4*)Wp)[i - nU];
        __half2 h0 = __floats2half2_rn(v.x, v.y);
        __half2 h1 = __floats2half2_rn(v.z, v.w);
        uint2 o;
        o.x = *(const uint32_t*)&h0;
        o.y = *(const uint32_t*)&h1;
        if (i < nU) ((uint2*)g_Uh)[i] = o;
        else        ((uint2*)g_Wh)[i - nU] = o;
    }
}

// ---------------------------------------------------------------------------
// Kernel 1: fp16 mma.sync GEMM + bias + SiLU -> g_uproj
// BM=128, BN=256, BK=32 halves, 3-stage cp.async, 8 warps (2x4), warp 64x64.
// Smem rows padded to 80B (odd*16 => ldmatrix conflict-free permutation).
// ---------------------------------------------------------------------------
#define BK 32
#define ROWB 80
#define A_STAGE (128 * ROWB)            // 10240
#define B_STAGE (256 * ROWB)            // 20480
#define STAGE_B (A_STAGE + B_STAGE)     // 30720
#define GEMM_SMEM (3 * STAGE_B)         // 92160

__device__ __forceinline__ void cp16(uint32_t dst, const void* src) {
    asm volatile("cp.async.cg.shared.global [%0], [%1], 16;"
                 :: "r"(dst), "l"(__cvta_generic_to_global(src)));
}

__device__ __forceinline__ void ldmatrix4(uint32_t* r, uint32_t addr) {
    asm volatile("ldmatrix.sync.aligned.m8n8.x4.shared.b16 {%0,%1,%2,%3}, [%4];"
                 : "=r"(r[0]), "=r"(r[1]), "=r"(r[2]), "=r"(r[3]) : "r"(addr));
}

__device__ __forceinline__ void mma16816(float* c, const uint32_t* a,
                                         uint32_t b0, uint32_t b1) {
    asm volatile(
        "mma.sync.aligned.m16n8k16.row.col.f32.f16.f16.f32 "
        "{%0,%1,%2,%3}, {%4,%5,%6,%7}, {%8,%9}, {%0,%1,%2,%3};"
        : "+f"(c[0]), "+f"(c[1]), "+f"(c[2]), "+f"(c[3])
        : "r"(a[0]), "r"(a[1]), "r"(a[2]), "r"(a[3]), "r"(b0), "r"(b1));
}

__global__ void __launch_bounds__(256, 1)
gemm_h_kernel(const float* __restrict__ bp)
{
    extern __shared__ __align__(128) char sm[];
    const uint32_t sbase = smem_u32(sm);
    const int tid  = threadIdx.x;
    const int lane = tid & 31;
    const int warp = tid >> 5;
    const int wm = warp >> 2;     // 0..1
    const int wn = warp & 3;      // 0..3

    const int t  = blockIdx.x;
    const int m0 = (t >> 2) * 128;
    const int n0 = (t & 3) * 256;

    float c[4][8][4];
    #pragma unroll
    for (int i = 0; i < 4; i++)
        #pragma unroll
        for (int j = 0; j < 8; j++)
            #pragma unroll
            for (int r = 0; r < 4; r++) c[i][j][r] = 0.0f;

    // stage loader: A 512 chunks (2/thread), B 1024 chunks (4/thread)
    auto load_stage = [&](int s, int kt) {
        uint32_t ab = sbase + s * STAGE_B;
        uint32_t bb = ab + A_STAGE;
        #pragma unroll
        for (int tt = 0; tt < 2; tt++) {
            int i = tid + tt * 256;
            int r = i >> 2, cb = i & 3;
            cp16(ab + r * ROWB + cb * 16,
                 g_Uh + (size_t)(m0 + r) * D_DIM + kt + cb * 8);
        }
        #pragma unroll
        for (int tt = 0; tt < 4; tt++) {
            int i = tid + tt * 256;
            int r = i >> 2, cb = i & 3;
            cp16(bb + r * ROWB + cb * 16,
                 g_Wh + (size_t)(n0 + r) * D_DIM + kt + cb * 8);
        }
    };

    load_stage(0, 0);
    asm volatile("cp.async.commit_group;");
    load_stage(1, BK);
    asm volatile("cp.async.commit_group;");

    // ldmatrix per-lane offsets
    const uint32_t a_lane = (uint32_t)(((lane & 7) + ((lane >> 3) & 1) * 8) * ROWB
                                       + ((lane >> 4) & 1) * 16);
    const uint32_t b_lane = (uint32_t)(((lane & 7) + ((lane >> 4) & 1) * 8) * ROWB
                                       + ((lane >> 3) & 1) * 16);

    for (int kc = 0; kc < 32; kc++) {
        asm volatile("cp.async.wait_group 1;" ::: "memory");
        __syncthreads();
        if (kc + 2 < 32) load_stage((kc + 2) % 3, (kc + 2) * BK);
        asm volatile("cp.async.commit_group;");

        const uint32_t ab = sbase + (kc % 3) * STAGE_B + (uint32_t)(wm * 64) * ROWB + a_lane;
        const uint32_t bb = sbase + (kc % 3) * STAGE_B + A_STAGE
                            + (uint32_t)(wn * 64) * ROWB + b_lane;
        #pragma unroll
        for (int kk = 0; kk < 2; kk++) {
            uint32_t ar[4][4], br[4][4];
            #pragma unroll
            for (int mt = 0; mt < 4; mt++)
                ldmatrix4(ar[mt], ab + mt * 16 * ROWB + kk * 32);
            #pragma unroll
            for (int n2 = 0; n2 < 4; n2++)
                ldmatrix4(br[n2], bb + n2 * 16 * ROWB + kk * 32);
            #pragma unroll
            for (int mt = 0; mt < 4; mt++)
                #pragma unroll
                for (int nt = 0; nt < 8; nt++) {
                    const uint32_t* b = br[nt >> 1];
                    if (nt & 1) mma16816(c[mt][nt], ar[mt], b[2], b[3]);
                    else        mma16816(c[mt][nt], ar[mt], b[0], b[1]);
                }
        }
    }

    // epilogue: + bias, silu, store
    const int g  = lane >> 2;
    const int tq = lane & 3;
    #pragma unroll
    for (int mt = 0; mt < 4; mt++) {
        const int row = m0 + wm * 64 + mt * 16 + g;
        #pragma unroll
        for (int nt = 0; nt < 8; nt++) {
            const int col = n0 + wn * 64 + nt * 8 + tq * 2;
            float2 bb = *(const float2*)(bp + col);
            float2 v0 = make_float2(silu_f(c[mt][nt][0] + bb.x),
                                    silu_f(c[mt][nt][1] + bb.y));
            float2 v1 = make_float2(silu_f(c[mt][nt][2] + bb.x),
                                    silu_f(c[mt][nt][3] + bb.y));
            *(float2*)(g_uproj + (size_t)row * D_DIM + col)       = v0;
            *(float2*)(g_uproj + (size_t)(row + 8) * D_DIM + col) = v1;
        }
    }
}

// ---------------------------------------------------------------------------
// Kernel 2: fused conv1(k=3)->silu->conv2(k=128), * u_proj.
// Channel pairs packed in f32x2 (FFMA2). Block = 32 pairs (64 ch) x 128 l.
// R=16 output rolling window: per tap 2x LDS.64 + 16 FFMA2.
// ---------------------------------------------------------------------------
#define CLT 128
#define CP  32
#define CHROWS (CLT + 128)
#define CONV_SMEM (CHROWS * CP * 8 + 128 * CP * 8)   // 96 KB

typedef unsigned long long ull;

__device__ __forceinline__ void ffma2(ull& d, ull a, ull b) {
    asm("fma.rn.f32x2 %0, %1, %2, %0;" : "+l"(d) : "l"(a), "l"(b));
}
__device__ __forceinline__ float2 unpack2(ull v) {
    float2 r;
    asm("mov.b64 {%0,%1}, %2;" : "=f"(r.x), "=f"(r.y) : "l"(v));
    return r;
}

__global__ void __launch_bounds__(256, 2)
conv_fused_kernel(const float* __restrict__ u,
                  const float* __restrict__ w1,
                  const float* __restrict__ b1,
                  const float* __restrict__ w2,
                  const float* __restrict__ b2,
                  float* __restrict__ out)
{
    extern __shared__ __align__(16) float cs[];
    float2* h_s  = (float2*)cs;                       // [256][32]
    float2* w2_s = (float2*)(cs + CHROWS * CP * 2);   // [128][32]

    const int c   = threadIdx.x;
    const int yy  = threadIdx.y;
    const int tid = c + yy * 32;

    const int chunk = blockIdx.x;
    const int lt    = blockIdx.y;
    const int bb    = blockIdx.z;
    const int tile_start = lt * CLT;
    const int p = chunk * CP + c;

    const float2* uf2  = (const float2*)u + (size_t)bb * L_SEQ * 512;
    const float2* w1f2 = (const float2*)w1;
    const float2* w2f2 = (const float2*)w2;

    #pragma unroll
    for (int i = tid; i < 128 * CP; i += 256) {
        int j = i >> 5, cc = i & 31;
        w2_s[j * CP + cc] = w2f2[(size_t)j * 512 + chunk * CP + cc];
    }

    const float2 w1_0 = w1f2[0 * 512 + p];
    const float2 w1_1 = w1f2[1 * 512 + p];
    const float2 w1_2 = w1f2[2 * 512 + p];
    const float2 b1c  = ((const float2*)b1)[p];

    for (int i = tid; i < CHROWS * CP; i += 256) {
        int hl = i >> 5;
        int l  = tile_start - 127 + hl;
        float2 hv = make_float2(0.0f, 0.0f);
        if (l >= 0 && l < L_SEQ) {
            float2 x2 = uf2[(size_t)l * 512 + p];
            float2 x1 = (l >= 1) ? uf2[(size_t)(l - 1) * 512 + p] : make_float2(0.f, 0.f);
            float2 x0 = (l >= 2) ? uf2[(size_t)(l - 2) * 512 + p] : make_float2(0.f, 0.f);
            float vx = fmaf(x0.x, w1_0.x, fmaf(x1.x, w1_1.x, fmaf(x2.x, w1_2.x, b1c.x)));
            float vy = fmaf(x0.y, w1_0.y, fmaf(x1.y, w1_1.y, fmaf(x2.y, w1_2.y, b1c.y)));
            hv.x = silu_f(vx);
            hv.y = silu_f(vy);
        }
        h_s[hl * CP + c] = hv;
    }
    __syncthreads();

    const int base = yy * 16;
    ull acc[16], win[16];
    #pragma unroll
    for (int r = 0; r < 16; r++) {
        acc[r] = 0ULL;
        win[r] = *(const ull*)&h_s[(base + r) * CP + c];
    }
    #pragma unroll 8
    for (int j = 0; j < 128; j++) {
        ull w = *(const ull*)&w2_s[j * CP + c];
        #pragma unroll
        for (int r = 0; r < 16; r++)
            ffma2(acc[r], win[(j + r) & 15], w);
        win[j & 15] = *(const ull*)&h_s[(base + j + 16) * CP + c];
    }

    const float2 b2c = ((const float2*)b2)[p];
    const float2* upf2 = (const float2*)g_uproj
                         + ((size_t)bb * L_SEQ + tile_start) * 512 + p;
    float2* opf2 = (float2*)out + ((size_t)bb * L_SEQ + tile_start) * 512 + p;

    #pragma unroll
    for (int r = 0; r < 16; r++) {
        float2 a  = unpack2(acc[r]);
        int lo    = base + r;
        float2 pr = upf2[(size_t)lo * 512];
        float2 y;
        y.x = (a.x + b2c.x) * pr.x;
        y.y = (a.y + b2c.y) * pr.y;
        opf2[(size_t)lo * 512] = y;
    }
}

// ---------------------------------------------------------------------------
extern "C" void kernel_launch(void* const* d_in, const int* in_sizes, int n_in,
                              void* d_out, int out_size)
{
    const float* u  = (const float*)d_in[0];
    const float* w1 = (const float*)d_in[1];
    const float* b1 = (const float*)d_in[2];
    const float* w2 = (const float*)d_in[3];
    const float* b2 = (const float*)d_in[4];
    const float* Wp = (const float*)d_in[5];
    const float* bp = (const float*)d_in[6];
    float* out = (float*)d_out;

    cudaFuncSetAttribute(gemm_h_kernel,
                         cudaFuncAttributeMaxDynamicSharedMemorySize, GEMM_SMEM);
    cudaFuncSetAttribute(conv_fused_kernel,
                         cudaFuncAttributeMaxDynamicSharedMemorySize, CONV_SMEM);

    convert_kernel<<<2048, 256>>>(u, Wp);
    gemm_h_kernel<<<512, 256, GEMM_SMEM>>>(bp);

    dim3 g2(D_DIM / (2 * CP), L_SEQ / CLT, BATCH);   // (16, 32, 4)
    conv_fused_kernel<<<g2, dim3(32, 8), CONV_SMEM>>>(u, w1, b1, w2, b2, out);
}

// round 4
// speedup vs baseline: 2.2570x; 1.0342x over previous
#include <cuda_runtime.h>
#include <cuda_fp16.h>
#include <cstdint>

#define L_SEQ 4096
#define D_DIM 1024
#define BATCH 4
#define M_TOT 16384

// scratch
__device__ float  g_uproj[(size_t)M_TOT * D_DIM];   // 64 MB
__device__ __half g_Uh[(size_t)M_TOT * D_DIM];      // 32 MB
__device__ __half g_Wh[(size_t)D_DIM * D_DIM];      // 2 MB

__device__ __forceinline__ float silu_f(float x) {
    return x / (1.0f + __expf(-x));
}

__device__ __forceinline__ uint32_t smem_u32(const void* p) {
    uint32_t a;
    asm("{ .reg .u64 t; cvta.to.shared.u64 t, %1; cvt.u32.u64 %0, t; }"
        : "=r"(a) : "l"(p));
    return a;
}

// ---------------------------------------------------------------------------
// Kernel 0: convert U and Wp to fp16 (RNE)
// ---------------------------------------------------------------------------
__global__ void __launch_bounds__(256)
convert_kernel(const float* __restrict__ U, const float* __restrict__ Wp)
{
    const size_t nU = (size_t)M_TOT * D_DIM / 4;
    const size_t nW = (size_t)D_DIM * D_DIM / 4;
    const size_t stride = (size_t)gridDim.x * blockDim.x;
    for (size_t i = (size_t)blockIdx.x * blockDim.x + threadIdx.x;
         i < nU + nW; i += stride) {
        float4 v = (i < nU) ? ((const float4*)U)[i] : ((const float4*)Wp)[i - nU];
        __half2 h0 = __floats2half2_rn(v.x, v.y);
        __half2 h1 = __floats2half2_rn(v.z, v.w);
        uint2 o;
        o.x = *(const uint32_t*)&h0;
        o.y = *(const uint32_t*)&h1;
        if (i < nU) ((uint2*)g_Uh)[i] = o;
        else        ((uint2*)g_Wh)[i - nU] = o;
    }
}

// ---------------------------------------------------------------------------
// Kernel 1: fp16 mma.sync GEMM + bias + SiLU -> g_uproj
// BM=128, BN=256, BK=32 halves, 3-stage cp.async pipeline.
// 512 threads / 16 warps (4x4), warp tile 32x64 -> 4 warps/SMSP, ~105 live regs.
// Smem rows padded to 80B (odd*16 => conflict-free ldmatrix).
// ---------------------------------------------------------------------------
#define BK 32
#define ROWB 80
#define A_STAGE (128 * ROWB)            // 10240
#define B_STAGE (256 * ROWB)            // 20480
#define STAGE_B (A_STAGE + B_STAGE)     // 30720
#define GEMM_SMEM (3 * STAGE_B)         // 92160

__device__ __forceinline__ void cp16(uint32_t dst, const void* src) {
    asm volatile("cp.async.cg.shared.global [%0], [%1], 16;"
                 :: "r"(dst), "l"(__cvta_generic_to_global(src)));
}

__device__ __forceinline__ void ldmatrix4(uint32_t* r, uint32_t addr) {
    asm volatile("ldmatrix.sync.aligned.m8n8.x4.shared.b16 {%0,%1,%2,%3}, [%4];"
                 : "=r"(r[0]), "=r"(r[1]), "=r"(r[2]), "=r"(r[3]) : "r"(addr));
}

__device__ __forceinline__ void mma16816(float* c, const uint32_t* a,
                                         uint32_t b0, uint32_t b1) {
    asm volatile(
        "mma.sync.aligned.m16n8k16.row.col.f32.f16.f16.f32 "
        "{%0,%1,%2,%3}, {%4,%5,%6,%7}, {%8,%9}, {%0,%1,%2,%3};"
        : "+f"(c[0]), "+f"(c[1]), "+f"(c[2]), "+f"(c[3])
        : "r"(a[0]), "r"(a[1]), "r"(a[2]), "r"(a[3]), "r"(b0), "r"(b1));
}

__global__ void __launch_bounds__(512, 1)
gemm_h_kernel(const float* __restrict__ bp)
{
    extern __shared__ __align__(128) char sm[];
    const uint32_t sbase = smem_u32(sm);
    const int tid  = threadIdx.x;
    const int lane = tid & 31;
    const int warp = tid >> 5;
    const int wm = warp >> 2;     // 0..3  (M 32-row slab)
    const int wn = warp & 3;      // 0..3  (N 64-col slab)

    const int t  = blockIdx.x;
    const int m0 = (t >> 2) * 128;
    const int n0 = (t & 3) * 256;

    float c[2][8][4];
    #pragma unroll
    for (int i = 0; i < 2; i++)
        #pragma unroll
        for (int j = 0; j < 8; j++)
            #pragma unroll
            for (int r = 0; r < 4; r++) c[i][j][r] = 0.0f;

    // stage loader: A 512 x 16B (1/thread), B 1024 x 16B (2/thread)
    auto load_stage = [&](int s, int kt) {
        uint32_t ab = sbase + s * STAGE_B;
        uint32_t bb = ab + A_STAGE;
        {
            int r = tid >> 2, cb = tid & 3;
            cp16(ab + r * ROWB + cb * 16,
                 g_Uh + (size_t)(m0 + r) * D_DIM + kt + cb * 8);
        }
        #pragma unroll
        for (int tt = 0; tt < 2; tt++) {
            int i = tid + tt * 512;
            int r = i >> 2, cb = i & 3;
            cp16(bb + r * ROWB + cb * 16,
                 g_Wh + (size_t)(n0 + r) * D_DIM + kt + cb * 8);
        }
    };

    load_stage(0, 0);
    asm volatile("cp.async.commit_group;");
    load_stage(1, BK);
    asm volatile("cp.async.commit_group;");

    // ldmatrix per-lane offsets (validated mapping from round 3)
    const uint32_t a_lane = (uint32_t)(((lane & 7) + ((lane >> 3) & 1) * 8) * ROWB
                                       + ((lane >> 4) & 1) * 16);
    const uint32_t b_lane = (uint32_t)(((lane & 7) + ((lane >> 4) & 1) * 8) * ROWB
                                       + ((lane >> 3) & 1) * 16);

    for (int kc = 0; kc < 32; kc++) {
        asm volatile("cp.async.wait_group 1;" ::: "memory");
        __syncthreads();
        if (kc + 2 < 32) load_stage((kc + 2) % 3, (kc + 2) * BK);
        asm volatile("cp.async.commit_group;");

        const uint32_t ab = sbase + (kc % 3) * STAGE_B
                            + (uint32_t)(wm * 32) * ROWB + a_lane;
        const uint32_t bb = sbase + (kc % 3) * STAGE_B + A_STAGE
                            + (uint32_t)(wn * 64) * ROWB + b_lane;
        #pragma unroll
        for (int kk = 0; kk < 2; kk++) {
            uint32_t ar[2][4];
            #pragma unroll
            for (int mt = 0; mt < 2; mt++)
                ldmatrix4(ar[mt], ab + mt * 16 * ROWB + kk * 32);
            #pragma unroll
            for (int bh = 0; bh < 4; bh++) {
                uint32_t br[4];
                ldmatrix4(br, bb + bh * 16 * ROWB + kk * 32);
                #pragma unroll
                for (int mt = 0; mt < 2; mt++) {
                    mma16816(c[mt][2 * bh + 0], ar[mt], br[0], br[1]);
                    mma16816(c[mt][2 * bh + 1], ar[mt], br[2], br[3]);
                }
            }
        }
    }

    // epilogue: + bias, silu, store
    const int g  = lane >> 2;
    const int tq = lane & 3;
    #pragma unroll
    for (int mt = 0; mt < 2; mt++) {
        const int row = m0 + wm * 32 + mt * 16 + g;
        #pragma unroll
        for (int nt = 0; nt < 8; nt++) {
            const int col = n0 + wn * 64 + nt * 8 + tq * 2;
            float2 bb = *(const float2*)(bp + col);
            float2 v0 = make_float2(silu_f(c[mt][nt][0] + bb.x),
                                    silu_f(c[mt][nt][1] + bb.y));
            float2 v1 = make_float2(silu_f(c[mt][nt][2] + bb.x),
                                    silu_f(c[mt][nt][3] + bb.y));
            *(float2*)(g_uproj + (size_t)row * D_DIM + col)       = v0;
            *(float2*)(g_uproj + (size_t)(row + 8) * D_DIM + col) = v1;
        }
    }
}

// ---------------------------------------------------------------------------
// Kernel 2: fused conv1(k=3)->silu->conv2(k=128), * u_proj.  (unchanged)
// ---------------------------------------------------------------------------
#define CLT 128
#define CP  32
#define CHROWS (CLT + 128)
#define CONV_SMEM (CHROWS * CP * 8 + 128 * CP * 8)   // 96 KB

typedef unsigned long long ull;

__device__ __forceinline__ void ffma2(ull& d, ull a, ull b) {
    asm("fma.rn.f32x2 %0, %1, %2, %0;" : "+l"(d) : "l"(a), "l"(b));
}
__device__ __forceinline__ float2 unpack2(ull v) {
    float2 r;
    asm("mov.b64 {%0,%1}, %2;" : "=f"(r.x), "=f"(r.y) : "l"(v));
    return r;
}

__global__ void __launch_bounds__(256, 2)
conv_fused_kernel(const float* __restrict__ u,
                  const float* __restrict__ w1,
                  const float* __restrict__ b1,
                  const float* __restrict__ w2,
                  const float* __restrict__ b2,
                  float* __restrict__ out)
{
    extern __shared__ __align__(16) float cs[];
    float2* h_s  = (float2*)cs;                       // [256][32]
    float2* w2_s = (float2*)(cs + CHROWS * CP * 2);   // [128][32]

    const int c   = threadIdx.x;
    const int yy  = threadIdx.y;
    const int tid = c + yy * 32;

    const int chunk = blockIdx.x;
    const int lt    = blockIdx.y;
    const int bb    = blockIdx.z;
    const int tile_start = lt * CLT;
    const int p = chunk * CP + c;

    const float2* uf2  = (const float2*)u + (size_t)bb * L_SEQ * 512;
    const float2* w1f2 = (const float2*)w1;
    const float2* w2f2 = (const float2*)w2;

    #pragma unroll
    for (int i = tid; i < 128 * CP; i += 256) {
        int j = i >> 5, cc = i & 31;
        w2_s[j * CP + cc] = w2f2[(size_t)j * 512 + chunk * CP + cc];
    }

    const float2 w1_0 = w1f2[0 * 512 + p];
    const float2 w1_1 = w1f2[1 * 512 + p];
    const float2 w1_2 = w1f2[2 * 512 + p];
    const float2 b1c  = ((const float2*)b1)[p];

    for (int i = tid; i < CHROWS * CP; i += 256) {
        int hl = i >> 5;
        int l  = tile_start - 127 + hl;
        float2 hv = make_float2(0.0f, 0.0f);
        if (l >= 0 && l < L_SEQ) {
            float2 x2 = uf2[(size_t)l * 512 + p];
            float2 x1 = (l >= 1) ? uf2[(size_t)(l - 1) * 512 + p] : make_float2(0.f, 0.f);
            float2 x0 = (l >= 2) ? uf2[(size_t)(l - 2) * 512 + p] : make_float2(0.f, 0.f);
            float vx = fmaf(x0.x, w1_0.x, fmaf(x1.x, w1_1.x, fmaf(x2.x, w1_2.x, b1c.x)));
            float vy = fmaf(x0.y, w1_0.y, fmaf(x1.y, w1_1.y, fmaf(x2.y, w1_2.y, b1c.y)));
            hv.x = silu_f(vx);
            hv.y = silu_f(vy);
        }
        h_s[hl * CP + c] = hv;
    }
    __syncthreads();

    const int base = yy * 16;
    ull acc[16], win[16];
    #pragma unroll
    for (int r = 0; r < 16; r++) {
        acc[r] = 0ULL;
        win[r] = *(const ull*)&h_s[(base + r) * CP + c];
    }
    #pragma unroll 8
    for (int j = 0; j < 128; j++) {
        ull w = *(const ull*)&w2_s[j * CP + c];
        #pragma unroll
        for (int r = 0; r < 16; r++)
            ffma2(acc[r], win[(j + r) & 15], w);
        win[j & 15] = *(const ull*)&h_s[(base + j + 16) * CP + c];
    }

    const float2 b2c = ((const float2*)b2)[p];
    const float2* upf2 = (const float2*)g_uproj
                         + ((size_t)bb * L_SEQ + tile_start) * 512 + p;
    float2* opf2 = (float2*)out + ((size_t)bb * L_SEQ + tile_start) * 512 + p;

    #pragma unroll
    for (int r = 0; r < 16; r++) {
        float2 a  = unpack2(acc[r]);
        int lo    = base + r;
        float2 pr = upf2[(size_t)lo * 512];
        float2 y;
        y.x = (a.x + b2c.x) * pr.x;
        y.y = (a.y + b2c.y) * pr.y;
        opf2[(size_t)lo * 512] = y;
    }
}

// ---------------------------------------------------------------------------
extern "C" void kernel_launch(void* const* d_in, const int* in_sizes, int n_in,
                              void* d_out, int out_size)
{
    const float* u  = (const float*)d_in[0];
    const float* w1 = (const float*)d_in[1];
    const float* b1 = (const float*)d_in[2];
    const float* w2 = (const float*)d_in[3];
    const float* b2 = (const float*)d_in[4];
    const float* Wp = (const float*)d_in[5];
    const float* bp = (const float*)d_in[6];
    float* out = (float*)d_out;

    cudaFuncSetAttribute(gemm_h_kernel,
                         cudaFuncAttributeMaxDynamicSharedMemorySize, GEMM_SMEM);
    cudaFuncSetAttribute(conv_fused_kernel,
                         cudaFuncAttributeMaxDynamicSharedMemorySize, CONV_SMEM);

    convert_kernel<<<2048, 256>>>(u, Wp);
    gemm_h_kernel<<<512, 512, GEMM_SMEM>>>(bp);

    dim3 g2(D_DIM / (2 * CP), L_SEQ / CLT, BATCH);   // (16, 32, 4)
    conv_fused_kernel<<<g2, dim3(32, 8), CONV_SMEM>>>(u, w1, b1, w2, b2, out);
}

// round 5
// speedup vs baseline: 2.6883x; 1.1911x over previous
#include <cuda_runtime.h>
#include <cuda_fp16.h>
#include <cstdint>

#define L_SEQ 4096
#define D_DIM 1024
#define BATCH 4
#define M_TOT 16384

// scratch
__device__ float  g_uproj[(size_t)M_TOT * D_DIM];   // 64 MB
__device__ __half g_Uh[(size_t)M_TOT * D_DIM];      // 32 MB
__device__ __half g_Wh[(size_t)D_DIM * D_DIM];      // 2 MB

__device__ __forceinline__ float silu_f(float x) {
    return x / (1.0f + __expf(-x));
}

__device__ __forceinline__ uint32_t smem_u32(const void* p) {
    uint32_t a;
    asm("{ .reg .u64 t; cvta.to.shared.u64 t, %1; cvt.u32.u64 %0, t; }"
        : "=r"(a) : "l"(p));
    return a;
}

// ---------------------------------------------------------------------------
// Kernel 0: convert U and Wp to fp16 (RNE)
// ---------------------------------------------------------------------------
__global__ void __launch_bounds__(256)
convert_kernel(const float* __restrict__ U, const float* __restrict__ Wp)
{
    const size_t nU = (size_t)M_TOT * D_DIM / 4;
    const size_t nW = (size_t)D_DIM * D_DIM / 4;
    const size_t stride = (size_t)gridDim.x * blockDim.x;
    for (size_t i = (size_t)blockIdx.x * blockDim.x + threadIdx.x;
         i < nU + nW; i += stride) {
        float4 v = (i < nU) ? ((const float4*)U)[i] : ((const float4*)Wp)[i - nU];
        __half2 h0 = __floats2half2_rn(v.x, v.y);
        __half2 h1 = __floats2half2_rn(v.z, v.w);
        uint2 o;
        o.x = *(const uint32_t*)&h0;
        o.y = *(const uint32_t*)&h1;
        if (i < nU) ((uint2*)g_Uh)[i] = o;
        else        ((uint2*)g_Wh)[i - nU] = o;
    }
}

// ---------------------------------------------------------------------------
// Heterogeneous kernel: bids [0,1024) = GEMM 128x128 tiles (tensor pipe),
// bids [1024,3072) = conv CTAs (fma/lds pipes). 256 threads each, 96KB smem,
// 2 CTAs/SM. Conv writes conv2+b2 to out; separate kernel multiplies uproj.
// ---------------------------------------------------------------------------
#define GEMM_CTAS 1024
#define CONV_CTAS 2048
#define BK 32
#define ROWB 80
#define A_STAGE (128 * ROWB)            // 10240
#define STAGE_B (2 * A_STAGE)           // 20480 (A + B, 128 rows each)
#define HET_SMEM 98304                  // conv needs 96KB; gemm uses 61440

__device__ __forceinline__ void cp16(uint32_t dst, const void* src) {
    asm volatile("cp.async.cg.shared.global [%0], [%1], 16;"
                 :: "r"(dst), "l"(__cvta_generic_to_global(src)));
}

__device__ __forceinline__ void ldmatrix4(uint32_t* r, uint32_t addr) {
    asm volatile("ldmatrix.sync.aligned.m8n8.x4.shared.b16 {%0,%1,%2,%3}, [%4];"
                 : "=r"(r[0]), "=r"(r[1]), "=r"(r[2]), "=r"(r[3]) : "r"(addr));
}

__device__ __forceinline__ void mma16816(float* c, const uint32_t* a,
                                         uint32_t b0, uint32_t b1) {
    asm volatile(
        "mma.sync.aligned.m16n8k16.row.col.f32.f16.f16.f32 "
        "{%0,%1,%2,%3}, {%4,%5,%6,%7}, {%8,%9}, {%0,%1,%2,%3};"
        : "+f"(c[0]), "+f"(c[1]), "+f"(c[2]), "+f"(c[3])
        : "r"(a[0]), "r"(a[1]), "r"(a[2]), "r"(a[3]), "r"(b0), "r"(b1));
}

// conv geometry
#define CLT 128
#define CP  32
#define CHROWS (CLT + 128)

typedef unsigned long long ull;

__device__ __forceinline__ void ffma2(ull& d, ull a, ull b) {
    asm("fma.rn.f32x2 %0, %1, %2, %0;" : "+l"(d) : "l"(a), "l"(b));
}
__device__ __forceinline__ float2 unpack2(ull v) {
    float2 r;
    asm("mov.b64 {%0,%1}, %2;" : "=f"(r.x), "=f"(r.y) : "l"(v));
    return r;
}

__device__ void gemm_part(char* sm, const float* __restrict__ bp)
{
    const uint32_t sbase = smem_u32(sm);
    const int tid  = threadIdx.x;
    const int lane = tid & 31;
    const int warp = tid >> 5;
    const int wm = warp & 3;      // 0..3  M 32-row slab
    const int wn = warp >> 2;     // 0..1  N 64-col slab

    const int t  = blockIdx.x;
    const int m0 = (t >> 3) * 128;
    const int n0 = (t & 7) * 128;

    float c[2][8][4];
    #pragma unroll
    for (int i = 0; i < 2; i++)
        #pragma unroll
        for (int j = 0; j < 8; j++)
            #pragma unroll
            for (int r = 0; r < 4; r++) c[i][j][r] = 0.0f;

    auto load_stage = [&](int s, int kt) {
        uint32_t ab = sbase + s * STAGE_B;
        uint32_t bb = ab + A_STAGE;
        #pragma unroll
        for (int tt = 0; tt < 2; tt++) {
            int i = tid + tt * 256;
            int r = i >> 2, cb = i & 3;
            cp16(ab + r * ROWB + cb * 16,
                 g_Uh + (size_t)(m0 + r) * D_DIM + kt + cb * 8);
            cp16(bb + r * ROWB + cb * 16,
                 g_Wh + (size_t)(n0 + r) * D_DIM + kt + cb * 8);
        }
    };

    load_stage(0, 0);
    asm volatile("cp.async.commit_group;");
    load_stage(1, BK);
    asm volatile("cp.async.commit_group;");

    const uint32_t a_lane = (uint32_t)(((lane & 7) + ((lane >> 3) & 1) * 8) * ROWB
                                       + ((lane >> 4) & 1) * 16);
    const uint32_t b_lane = (uint32_t)(((lane & 7) + ((lane >> 4) & 1) * 8) * ROWB
                                       + ((lane >> 3) & 1) * 16);

    for (int kc = 0; kc < 32; kc++) {
        asm volatile("cp.async.wait_group 1;" ::: "memory");
        __syncthreads();
        if (kc + 2 < 32) load_stage((kc + 2) % 3, (kc + 2) * BK);
        asm volatile("cp.async.commit_group;");

        const uint32_t ab = sbase + (kc % 3) * STAGE_B
                            + (uint32_t)(wm * 32) * ROWB + a_lane;
        const uint32_t bb = sbase + (kc % 3) * STAGE_B + A_STAGE
                            + (uint32_t)(wn * 64) * ROWB + b_lane;
        #pragma unroll
        for (int kk = 0; kk < 2; kk++) {
            uint32_t ar[2][4];
            #pragma unroll
            for (int mt = 0; mt < 2; mt++)
                ldmatrix4(ar[mt], ab + mt * 16 * ROWB + kk * 32);
            #pragma unroll
            for (int bh = 0; bh < 4; bh++) {
                uint32_t br[4];
                ldmatrix4(br, bb + bh * 16 * ROWB + kk * 32);
                #pragma unroll
                for (int mt = 0; mt < 2; mt++) {
                    mma16816(c[mt][2 * bh + 0], ar[mt], br[0], br[1]);
                    mma16816(c[mt][2 * bh + 1], ar[mt], br[2], br[3]);
                }
            }
        }
    }

    const int g  = lane >> 2;
    const int tq = lane & 3;
    #pragma unroll
    for (int mt = 0; mt < 2; mt++) {
        const int row = m0 + wm * 32 + mt * 16 + g;
        #pragma unroll
        for (int nt = 0; nt < 8; nt++) {
            const int col = n0 + wn * 64 + nt * 8 + tq * 2;
            float2 bb = *(const float2*)(bp + col);
            float2 v0 = make_float2(silu_f(c[mt][nt][0] + bb.x),
                                    silu_f(c[mt][nt][1] + bb.y));
            float2 v1 = make_float2(silu_f(c[mt][nt][2] + bb.x),
                                    silu_f(c[mt][nt][3] + bb.y));
            *(float2*)(g_uproj + (size_t)row * D_DIM + col)       = v0;
            *(float2*)(g_uproj + (size_t)(row + 8) * D_DIM + col) = v1;
        }
    }
}

__device__ void conv_part(char* smc,
                          const float* __restrict__ u,
                          const float* __restrict__ w1,
                          const float* __restrict__ b1,
                          const float* __restrict__ w2,
                          const float* __restrict__ b2,
                          float* __restrict__ out)
{
    float2* h_s  = (float2*)smc;                              // [256][32]
    float2* w2_s = (float2*)(smc + CHROWS * CP * 8);          // [128][32]

    const int tid = threadIdx.x;
    const int c   = tid & 31;
    const int yy  = tid >> 5;

    const int idx   = blockIdx.x - GEMM_CTAS;
    const int chunk = idx & 15;
    const int lt    = (idx >> 4) & 31;
    const int bb    = idx >> 9;
    const int tile_start = lt * CLT;
    const int p = chunk * CP + c;

    const float2* uf2  = (const float2*)u + (size_t)bb * L_SEQ * 512;
    const float2* w1f2 = (const float2*)w1;
    const float2* w2f2 = (const float2*)w2;

    #pragma unroll
    for (int i = tid; i < 128 * CP; i += 256) {
        int j = i >> 5, cc = i & 31;
        w2_s[j * CP + cc] = w2f2[(size_t)j * 512 + chunk * CP + cc];
    }

    const float2 w1_0 = w1f2[0 * 512 + p];
    const float2 w1_1 = w1f2[1 * 512 + p];
    const float2 w1_2 = w1f2[2 * 512 + p];
    const float2 b1c  = ((const float2*)b1)[p];

    for (int i = tid; i < CHROWS * CP; i += 256) {
        int hl = i >> 5;
        int l  = tile_start - 127 + hl;
        float2 hv = make_float2(0.0f, 0.0f);
        if (l >= 0 && l < L_SEQ) {
            float2 x2 = uf2[(size_t)l * 512 + p];
            float2 x1 = (l >= 1) ? uf2[(size_t)(l - 1) * 512 + p] : make_float2(0.f, 0.f);
            float2 x0 = (l >= 2) ? uf2[(size_t)(l - 2) * 512 + p] : make_float2(0.f, 0.f);
            float vx = fmaf(x0.x, w1_0.x, fmaf(x1.x, w1_1.x, fmaf(x2.x, w1_2.x, b1c.x)));
            float vy = fmaf(x0.y, w1_0.y, fmaf(x1.y, w1_1.y, fmaf(x2.y, w1_2.y, b1c.y)));
            hv.x = silu_f(vx);
            hv.y = silu_f(vy);
        }
        h_s[hl * CP + c] = hv;
    }
    __syncthreads();

    const int base = yy * 16;
    ull acc[16], win[16];
    #pragma unroll
    for (int r = 0; r < 16; r++) {
        acc[r] = 0ULL;
        win[r] = *(const ull*)&h_s[(base + r) * CP + c];
    }
    #pragma unroll 8
    for (int j = 0; j < 128; j++) {
        ull w = *(const ull*)&w2_s[j * CP + c];
        #pragma unroll
        for (int r = 0; r < 16; r++)
            ffma2(acc[r], win[(j + r) & 15], w);
        win[j & 15] = *(const ull*)&h_s[(base + j + 16) * CP + c];
    }

    const float2 b2c = ((const float2*)b2)[p];
    float2* opf2 = (float2*)out + ((size_t)bb * L_SEQ + tile_start) * 512 + p;

    // store conv2 + b2 (projection multiply applied by mult_kernel)
    #pragma unroll
    for (int r = 0; r < 16; r++) {
        float2 a = unpack2(acc[r]);
        int lo   = base + r;
        float2 y;
        y.x = a.x + b2c.x;
        y.y = a.y + b2c.y;
        opf2[(size_t)lo * 512] = y;
    }
}

__global__ void __launch_bounds__(256, 2)
hetero_kernel(const float* __restrict__ u,
              const float* __restrict__ w1,
              const float* __restrict__ b1,
              const float* __restrict__ w2,
              const float* __restrict__ b2,
              const float* __restrict__ bp,
              float* __restrict__ out)
{
    extern __shared__ __align__(128) char sm[];
    if (blockIdx.x < GEMM_CTAS)
        gemm_part(sm, bp);
    else
        conv_part(sm, u, w1, b1, w2, b2, out);
}

// ---------------------------------------------------------------------------
// Final: out *= uproj (in place)
// ---------------------------------------------------------------------------
__global__ void __launch_bounds__(256)
mult_kernel(float* __restrict__ out)
{
    const size_t n4 = (size_t)M_TOT * D_DIM / 4;
    const size_t stride = (size_t)gridDim.x * blockDim.x;
    for (size_t i = (size_t)blockIdx.x * blockDim.x + threadIdx.x;
         i < n4; i += stride) {
        float4 o = ((const float4*)out)[i];
        float4 p = ((const float4*)g_uproj)[i];
        o.x *= p.x; o.y *= p.y; o.z *= p.z; o.w *= p.w;
        ((float4*)out)[i] = o;
    }
}

// ---------------------------------------------------------------------------
extern "C" void kernel_launch(void* const* d_in, const int* in_sizes, int n_in,
                              void* d_out, int out_size)
{
    const float* u  = (const float*)d_in[0];
    const float* w1 = (const float*)d_in[1];
    const float* b1 = (const float*)d_in[2];
    const float* w2 = (const float*)d_in[3];
    const float* b2 = (const float*)d_in[4];
    const float* Wp = (const float*)d_in[5];
    const float* bp = (const float*)d_in[6];
    float* out = (float*)d_out;

    cudaFuncSetAttribute(hetero_kernel,
                         cudaFuncAttributeMaxDynamicSharedMemorySize, HET_SMEM);

    convert_kernel<<<2048, 256>>>(u, Wp);
    hetero_kernel<<<GEMM_CTAS + CONV_CTAS, 256, HET_SMEM>>>(u, w1, b1, w2, b2, bp, out);
    mult_kernel<<<2048, 256>>>(out);
}

// round 6
// speedup vs baseline: 2.8406x; 1.0567x over previous
#include <cuda_runtime.h>
#include <cuda_fp16.h>
#include <cstdint>

#define L_SEQ 4096
#define D_DIM 1024
#define BATCH 4
#define M_TOT 16384

// scratch
__device__ float  g_uproj[(size_t)M_TOT * D_DIM];   // 64 MB
// tiled fp16: [tile][kc][row 128][64B], 8KB per (tile,kc) block, swizzled
__device__ __align__(16) __half g_Uh[(size_t)M_TOT * D_DIM];  // 32 MB
__device__ __align__(16) __half g_Wh[(size_t)D_DIM * D_DIM];  // 2 MB

__device__ __forceinline__ float silu_f(float x) {
    return x / (1.0f + __expf(-x));
}

__device__ __forceinline__ uint32_t smem_u32(const void* p) {
    uint32_t a;
    asm("{ .reg .u64 t; cvta.to.shared.u64 t, %1; cvt.u32.u64 %0, t; }"
        : "=r"(a) : "l"(p));
    return a;
}

// ---------------------------------------------------------------------------
// Kernel 0: convert U, Wp to fp16 in tiled+swizzled layout.
// index i -> (tile, kc, r, c): writes 8 rows x 64B contiguous per warp.
// ---------------------------------------------------------------------------
#define NCH_U (M_TOT * 128)     // 16B-chunks for U: 16384 rows * 128
#define NCH_W (D_DIM * 128)

__global__ void __launch_bounds__(256)
convert_kernel(const float* __restrict__ U, const float* __restrict__ Wp)
{
    const int stride = gridDim.x * blockDim.x;
    for (int i = blockIdx.x * blockDim.x + threadIdx.x;
         i < NCH_U + NCH_W; i += stride) {
        int j; const float* src; __half* dstbase;
        if (i < NCH_U) { j = i; src = U; dstbase = g_Uh; }
        else           { j = i - NCH_U; src = Wp; dstbase = g_Wh; }
        const int c    = j & 3;
        const int r    = (j >> 2) & 127;
        const int kc   = (j >> 9) & 31;
        const int tile = j >> 14;
        const int m    = tile * 128 + r;
        const float4* s = (const float4*)(src + (size_t)m * D_DIM + kc * 32 + c * 8);
        float4 v0 = s[0], v1 = s[1];
        __half2 h0 = __floats2half2_rn(v0.x, v0.y);
        __half2 h1 = __floats2half2_rn(v0.z, v0.w);
        __half2 h2 = __floats2half2_rn(v1.x, v1.y);
        __half2 h3 = __floats2half2_rn(v1.z, v1.w);
        uint4 o;
        o.x = *(const uint32_t*)&h0; o.y = *(const uint32_t*)&h1;
        o.z = *(const uint32_t*)&h2; o.w = *(const uint32_t*)&h3;
        const int csw = c ^ ((r >> 1) & 3);
        const size_t half_off = ((size_t)(tile * 32 + kc) << 12)   // 8KB block /2
                              + (size_t)r * 32 + csw * 8;
        *(uint4*)(dstbase + half_off) = o;
    }
}

// ---------------------------------------------------------------------------
// Heterogeneous kernel: bids [0,1024) = GEMM 128x128 tiles (tensor pipe),
// bids [1024,3072) = conv CTAs (fma/lds pipes).
// GEMM staging: cp.async.bulk (2 x 8KB per kc, single-thread issue) + mbarrier.
// ---------------------------------------------------------------------------
#define GEMM_CTAS 1024
#define CONV_CTAS 2048
#define STAGE_SZ 16384          // A 8KB + B 8KB
#define SM_MBAR  49152          // 3 mbarriers
#define HET_SMEM 98304          // conv needs 96KB

#define MBAR_INIT(mbar, cnt) \
    asm volatile("mbarrier.init.shared.b64 [%0], %1;" \
                 :: "r"((uint32_t)(mbar)), "r"((uint32_t)(cnt)) : "memory")
#define MBAR_EXPECT_TX(mbar, bytes) \
    asm volatile("mbarrier.arrive.expect_tx.shared.b64 _, [%0], %1;" \
                 :: "r"((uint32_t)(mbar)), "r"((uint32_t)(bytes)) : "memory")
#define MBAR_WAIT(mbar, ph) do { \
    uint32_t _m = (uint32_t)(mbar); uint32_t _p = (uint32_t)(ph); \
    asm volatile("{\n\t.reg .pred P1;\n\t" \
        "W_%=:\n\t" \
        "mbarrier.try_wait.parity.acquire.cta.shared::cta.b64 P1, [%0], %1, 0x989680;\n\t" \
        "@P1 bra.uni D_%=;\n\t" \
        "bra.uni W_%=;\n\t" \
        "D_%=:\n\t}" :: "r"(_m), "r"(_p) : "memory"); \
} while (0)

__device__ __forceinline__ void bulk_cp(uint32_t dst, const void* src,
                                        uint32_t bytes, uint32_t mbar) {
    asm volatile(
        "cp.async.bulk.shared::cta.global.mbarrier::complete_tx::bytes "
        "[%0], [%1], %2, [%3];"
        :: "r"(dst), "l"(__cvta_generic_to_global(src)), "r"(bytes), "r"(mbar)
        : "memory");
}

__device__ __forceinline__ void ldmatrix4(uint32_t* r, uint32_t addr) {
    asm volatile("ldmatrix.sync.aligned.m8n8.x4.shared.b16 {%0,%1,%2,%3}, [%4];"
                 : "=r"(r[0]), "=r"(r[1]), "=r"(r[2]), "=r"(r[3]) : "r"(addr));
}

__device__ __forceinline__ void mma16816(float* c, const uint32_t* a,
                                         uint32_t b0, uint32_t b1) {
    asm volatile(
        "mma.sync.aligned.m16n8k16.row.col.f32.f16.f16.f32 "
        "{%0,%1,%2,%3}, {%4,%5,%6,%7}, {%8,%9}, {%0,%1,%2,%3};"
        : "+f"(c[0]), "+f"(c[1]), "+f"(c[2]), "+f"(c[3])
        : "r"(a[0]), "r"(a[1]), "r"(a[2]), "r"(a[3]), "r"(b0), "r"(b1));
}

// conv geometry
#define CLT 128
#define CP  32
#define CHROWS (CLT + 128)

typedef unsigned long long ull;

__device__ __forceinline__ void ffma2(ull& d, ull a, ull b) {
    asm("fma.rn.f32x2 %0, %1, %2, %0;" : "+l"(d) : "l"(a), "l"(b));
}
__device__ __forceinline__ float2 unpack2(ull v) {
    float2 r;
    asm("mov.b64 {%0,%1}, %2;" : "=f"(r.x), "=f"(r.y) : "l"(v));
    return r;
}

__device__ void gemm_part(char* sm, const float* __restrict__ bp)
{
    const uint32_t sbase = smem_u32(sm);
    const uint32_t mb    = sbase + SM_MBAR;
    const int tid  = threadIdx.x;
    const int lane = tid & 31;
    const int warp = tid >> 5;
    const int wm = warp & 3;      // 0..3  M 32-row slab
    const int wn = warp >> 2;     // 0..1  N 64-col slab

    const int t      = blockIdx.x;
    const int tile_m = t >> 3;
    const int tile_n = t & 7;
    const int m0 = tile_m * 128;
    const int n0 = tile_n * 128;

    float c[2][8][4];
    #pragma unroll
    for (int i = 0; i < 2; i++)
        #pragma unroll
        for (int j = 0; j < 8; j++)
            #pragma unroll
            for (int r = 0; r < 4; r++) c[i][j][r] = 0.0f;

    // precompute per-lane ldmatrix offsets (swizzled, row stride 64B)
    int offA[2][2], offB[4][2];
    {
        const int c0a = (lane >> 4) & 1;
        const int c0b = (lane >> 3) & 1;
        #pragma unroll
        for (int mt = 0; mt < 2; mt++) {
            int rA = wm * 32 + mt * 16 + (lane & 7) + ((lane >> 3) & 1) * 8;
            int sw = (rA >> 1) & 3;
            #pragma unroll
            for (int kk = 0; kk < 2; kk++)
                offA[mt][kk] = rA * 64 + (((c0a | (kk << 1)) ^ sw) << 4);
        }
        #pragma unroll
        for (int bh = 0; bh < 4; bh++) {
            int rB = wn * 64 + bh * 16 + (lane & 7) + ((lane >> 4) & 1) * 8;
            int sw = (rB >> 1) & 3;
            #pragma unroll
            for (int kk = 0; kk < 2; kk++)
                offB[bh][kk] = 8192 + rB * 64 + (((c0b | (kk << 1)) ^ sw) << 4);
        }
    }

    const char* Abase = (const char*)g_Uh + (size_t)tile_m * 32 * 8192;
    const char* Bbase = (const char*)g_Wh + (size_t)tile_n * 32 * 8192;

    if (tid == 0) {
        MBAR_INIT(mb + 0, 1);
        MBAR_INIT(mb + 8, 1);
        MBAR_INIT(mb + 16, 1);
        asm volatile("fence.proxy.async.shared::cta;" ::: "memory");
        #pragma unroll
        for (int k0 = 0; k0 < 2; k0++) {
            MBAR_EXPECT_TX(mb + k0 * 8, STAGE_SZ);
            bulk_cp(sbase + k0 * STAGE_SZ,        Abase + (size_t)k0 * 8192,
                    8192, mb + k0 * 8);
            bulk_cp(sbase + k0 * STAGE_SZ + 8192, Bbase + (size_t)k0 * 8192,
                    8192, mb + k0 * 8);
        }
    }
    __syncthreads();

    for (int kc = 0; kc < 32; kc++) {
        const int s = kc % 3;
        MBAR_WAIT(mb + s * 8, (kc / 3) & 1);
        __syncthreads();
        if (tid == 0 && kc + 2 < 32) {
            const int slot = (kc + 2) % 3;
            asm volatile("fence.proxy.async.shared::cta;" ::: "memory");
            MBAR_EXPECT_TX(mb + slot * 8, STAGE_SZ);
            bulk_cp(sbase + slot * STAGE_SZ,        Abase + (size_t)(kc + 2) * 8192,
                    8192, mb + slot * 8);
            bulk_cp(sbase + slot * STAGE_SZ + 8192, Bbase + (size_t)(kc + 2) * 8192,
                    8192, mb + slot * 8);
        }

        const uint32_t stage = sbase + s * STAGE_SZ;
        #pragma unroll
        for (int kk = 0; kk < 2; kk++) {
            uint32_t ar[2][4];
            #pragma unroll
            for (int mt = 0; mt < 2; mt++)
                ldmatrix4(ar[mt], stage + offA[mt][kk]);
            #pragma unroll
            for (int bh = 0; bh < 4; bh++) {
                uint32_t br[4];
                ldmatrix4(br, stage + offB[bh][kk]);
                #pragma unroll
                for (int mt = 0; mt < 2; mt++) {
                    mma16816(c[mt][2 * bh + 0], ar[mt], br[0], br[1]);
                    mma16816(c[mt][2 * bh + 1], ar[mt], br[2], br[3]);
                }
            }
        }
    }

    const int g  = lane >> 2;
    const int tq = lane & 3;
    #pragma unroll
    for (int mt = 0; mt < 2; mt++) {
        const int row = m0 + wm * 32 + mt * 16 + g;
        #pragma unroll
        for (int nt = 0; nt < 8; nt++) {
            const int col = n0 + wn * 64 + nt * 8 + tq * 2;
            float2 bb = *(const float2*)(bp + col);
            float2 v0 = make_float2(silu_f(c[mt][nt][0] + bb.x),
                                    silu_f(c[mt][nt][1] + bb.y));
            float2 v1 = make_float2(silu_f(c[mt][nt][2] + bb.x),
                                    silu_f(c[mt][nt][3] + bb.y));
            *(float2*)(g_uproj + (size_t)row * D_DIM + col)       = v0;
            *(float2*)(g_uproj + (size_t)(row + 8) * D_DIM + col) = v1;
        }
    }
}

__device__ void conv_part(char* smc,
                          const float* __restrict__ u,
                          const float* __restrict__ w1,
                          const float* __restrict__ b1,
                          const float* __restrict__ w2,
                          const float* __restrict__ b2,
                          float* __restrict__ out)
{
    float2* h_s  = (float2*)smc;                              // [256][32]
    float2* w2_s = (float2*)(smc + CHROWS * CP * 8);          // [128][32]

    const int tid = threadIdx.x;
    const int c   = tid & 31;
    const int yy  = tid >> 5;

    const int idx   = blockIdx.x - GEMM_CTAS;
    const int chunk = idx & 15;
    const int lt    = (idx >> 4) & 31;
    const int bb    = idx >> 9;
    const int tile_start = lt * CLT;
    const int p = chunk * CP + c;

    const float2* uf2  = (const float2*)u + (size_t)bb * L_SEQ * 512;
    const float2* w1f2 = (const float2*)w1;
    const float2* w2f2 = (const float2*)w2;

    #pragma unroll
    for (int i = tid; i < 128 * CP; i += 256) {
        int j = i >> 5, cc = i & 31;
        w2_s[j * CP + cc] = w2f2[(size_t)j * 512 + chunk * CP + cc];
    }

    const float2 w1_0 = w1f2[0 * 512 + p];
    const float2 w1_1 = w1f2[1 * 512 + p];
    const float2 w1_2 = w1f2[2 * 512 + p];
    const float2 b1c  = ((const float2*)b1)[p];

    for (int i = tid; i < CHROWS * CP; i += 256) {
        int hl = i >> 5;
        int l  = tile_start - 127 + hl;
        float2 hv = make_float2(0.0f, 0.0f);
        if (l >= 0 && l < L_SEQ) {
            float2 x2 = uf2[(size_t)l * 512 + p];
            float2 x1 = (l >= 1) ? uf2[(size_t)(l - 1) * 512 + p] : make_float2(0.f, 0.f);
            float2 x0 = (l >= 2) ? uf2[(size_t)(l - 2) * 512 + p] : make_float2(0.f, 0.f);
            float vx = fmaf(x0.x, w1_0.x, fmaf(x1.x, w1_1.x, fmaf(x2.x, w1_2.x, b1c.x)));
            float vy = fmaf(x0.y, w1_0.y, fmaf(x1.y, w1_1.y, fmaf(x2.y, w1_2.y, b1c.y)));
            hv.x = silu_f(vx);
            hv.y = silu_f(vy);
        }
        h_s[hl * CP + c] = hv;
    }
    __syncthreads();

    const int base = yy * 16;
    ull acc[16], win[16];
    #pragma unroll
    for (int r = 0; r < 16; r++) {
        acc[r] = 0ULL;
        win[r] = *(const ull*)&h_s[(base + r) * CP + c];
    }
    #pragma unroll 8
    for (int j = 0; j < 128; j++) {
        ull w = *(const ull*)&w2_s[j * CP + c];
        #pragma unroll
        for (int r = 0; r < 16; r++)
            ffma2(acc[r], win[(j + r) & 15], w);
        win[j & 15] = *(const ull*)&h_s[(base + j + 16) * CP + c];
    }

    const float2 b2c = ((const float2*)b2)[p];
    float2* opf2 = (float2*)out + ((size_t)bb * L_SEQ + tile_start) * 512 + p;

    #pragma unroll
    for (int r = 0; r < 16; r++) {
        float2 a = unpack2(acc[r]);
        int lo   = base + r;
        float2 y;
        y.x = a.x + b2c.x;
        y.y = a.y + b2c.y;
        opf2[(size_t)lo * 512] = y;
    }
}

__global__ void __launch_bounds__(256, 2)
hetero_kernel(const float* __restrict__ u,
              const float* __restrict__ w1,
              const float* __restrict__ b1,
              const float* __restrict__ w2,
              const float* __restrict__ b2,
              const float* __restrict__ bp,
              float* __restrict__ out)
{
    extern __shared__ __align__(128) char sm[];
    if (blockIdx.x < GEMM_CTAS)
        gemm_part(sm, bp);
    else
        conv_part(sm, u, w1, b1, w2, b2, out);
}

// ---------------------------------------------------------------------------
// Final: out *= uproj (in place)
// ---------------------------------------------------------------------------
__global__ void __launch_bounds__(256)
mult_kernel(float* __restrict__ out)
{
    const size_t n4 = (size_t)M_TOT * D_DIM / 4;
    const size_t stride = (size_t)gridDim.x * blockDim.x;
    for (size_t i = (size_t)blockIdx.x * blockDim.x + threadIdx.x;
         i < n4; i += stride) {
        float4 o = ((const float4*)out)[i];
        float4 p = ((const float4*)g_uproj)[i];
        o.x *= p.x; o.y *= p.y; o.z *= p.z; o.w *= p.w;
        ((float4*)out)[i] = o;
    }
}

// ---------------------------------------------------------------------------
extern "C" void kernel_launch(void* const* d_in, const int* in_sizes, int n_in,
                              void* d_out, int out_size)
{
    const float* u  = (const float*)d_in[0];
    const float* w1 = (const float*)d_in[1];
    const float* b1 = (const float*)d_in[2];
    const float* w2 = (const float*)d_in[3];
    const float* b2 = (const float*)d_in[4];
    const float* Wp = (const float*)d_in[5];
    const float* bp = (const float*)d_in[6];
    float* out = (float*)d_out;

    cudaFuncSetAttribute(hetero_kernel,
                         cudaFuncAttributeMaxDynamicSharedMemorySize, HET_SMEM);

    convert_kernel<<<2048, 256>>>(u, Wp);
    hetero_kernel<<<GEMM_CTAS + CONV_CTAS, 256, HET_SMEM>>>(u, w1, b1, w2, b2, bp, out);
    mult_kernel<<<2048, 256>>>(out);
}